// round 1
// baseline (speedup 1.0000x reference)
#include <cuda_runtime.h>

#define TSTEPS 65536
#define DTF (5.0f/60.0f)

// 8 MB log of h_t (state at the START of step t) for the observer pass.
__device__ float g_hs[(size_t)TSTEPS * 32];

typedef unsigned long long ull;

__device__ __forceinline__ ull pk2(float lo, float hi) {
    ull r; asm("mov.b64 %0, {%1,%2};" : "=l"(r) : "f"(lo), "f"(hi)); return r;
}
__device__ __forceinline__ float2 upk2(ull v) {
    float2 r; asm("mov.b64 {%0,%1}, %2;" : "=f"(r.x), "=f"(r.y) : "l"(v)); return r;
}
// Packed fp32x2 FMA (Blackwell): 2 fp32 MACs per instruction.
__device__ __forceinline__ ull ffma2(ull a, ull b, ull c) {
    ull d; asm("fma.rn.f32x2 %0, %1, %2, %3;" : "=l"(d) : "l"(a), "l"(b), "l"(c)); return d;
}

__device__ __forceinline__ float silu_f(float x) {
    float e = __expf(-x);
    return __fdividef(x, 1.0f + e);
}
__device__ __forceinline__ float tanh_f(float x) {
    float e = __expf(2.0f * x);
    return 1.0f - __fdividef(2.0f, e + 1.0f);
}

__global__ __launch_bounds__(128, 1)
void node_scan_kernel(const float* __restrict__ U, const float* __restrict__ h0,
                      const float* __restrict__ W1, const float* __restrict__ b1,
                      const float* __restrict__ W2, const float* __restrict__ b2,
                      const float* __restrict__ W3, const float* __restrict__ b3,
                      float* __restrict__ out)
{
    __shared__ __align__(16) float sx[40];    // MLP input: [h_eval(32), u(8)]
    __shared__ __align__(16) float sz1[128];
    __shared__ __align__(16) float sz2[128];
    __shared__ __align__(16) float sp[128];   // layer-3 partials

    const int j    = threadIdx.x;
    const int lane = j & 31;
    const int g    = j >> 5;

    // ---- register-resident weights (packed fp32 pairs) ----
    ull w1p[20];
#pragma unroll
    for (int m = 0; m < 20; m++)
        w1p[m] = pk2(W1[(2*m)*128 + j], W1[(2*m+1)*128 + j]);
    const float b1j = b1[j];

    ull w2p[64];
#pragma unroll
    for (int m = 0; m < 64; m++)
        w2p[m] = pk2(W2[(2*m)*128 + j], W2[(2*m+1)*128 + j]);
    const float b2j = b2[j];

    ull w3p[16];
#pragma unroll
    for (int m = 0; m < 16; m++)
        w3p[m] = pk2(W3[(32*g + 2*m)*32 + lane], W3[(32*g + 2*m + 1)*32 + lane]);

    float b3k = 0.0f, hreg = 0.0f;
    if (j < 32) { b3k = b3[j]; hreg = h0[j]; sx[j] = hreg; }

    // u double-buffer: ubuf holds u[t+1] during step t (threads 0,1 only)
    float4 ubuf = make_float4(0.f, 0.f, 0.f, 0.f);
    if (j < 2) {
        float4 u0 = ((const float4*)U)[j];       // u[0]
        ((float4*)(sx + 32))[j] = u0;
        ubuf = ((const float4*)U)[2 + j];        // u[1]
    }
    __syncthreads();

    float accK = 0.0f;

#pragma unroll 1
    for (int t = 0; t < TSTEPS; t++) {
        // log pre-update state for the observer pass (fire-and-forget)
        if (j < 32) g_hs[(size_t)t * 32 + j] = hreg;

#pragma unroll
        for (int s = 0; s < 4; s++) {
            // ---- layer 1: 40 -> 128, silu ----
            ull a0 = 0, a1 = 0, a2 = 0, a3 = 0;
            const ulonglong2* xv = (const ulonglong2*)sx;   // 10 entries
#pragma unroll
            for (int m = 0; m < 5; m++) {
                ulonglong2 p = xv[2*m];
                ulonglong2 q = xv[2*m + 1];
                a0 = ffma2(p.x, w1p[4*m + 0], a0);
                a1 = ffma2(p.y, w1p[4*m + 1], a1);
                a2 = ffma2(q.x, w1p[4*m + 2], a2);
                a3 = ffma2(q.y, w1p[4*m + 3], a3);
            }
            float2 f0 = upk2(a0), f1 = upk2(a1), f2 = upk2(a2), f3 = upk2(a3);
            float z = b1j + ((f0.x + f0.y) + (f1.x + f1.y))
                          + ((f2.x + f2.y) + (f3.x + f3.y));
            sz1[j] = silu_f(z);
            __syncthreads();

            // ---- layer 2: 128 -> 128, silu ----
            a0 = a1 = a2 = a3 = 0;
            const ulonglong2* zv = (const ulonglong2*)sz1;  // 32 entries
#pragma unroll
            for (int m = 0; m < 16; m++) {
                ulonglong2 p = zv[2*m];
                ulonglong2 q = zv[2*m + 1];
                a0 = ffma2(p.x, w2p[4*m + 0], a0);
                a1 = ffma2(p.y, w2p[4*m + 1], a1);
                a2 = ffma2(q.x, w2p[4*m + 2], a2);
                a3 = ffma2(q.y, w2p[4*m + 3], a3);
            }
            f0 = upk2(a0); f1 = upk2(a1); f2 = upk2(a2); f3 = upk2(a3);
            z = b2j + ((f0.x + f0.y) + (f1.x + f1.y))
                    + ((f2.x + f2.y) + (f3.x + f3.y));
            sz2[j] = silu_f(z);
            __syncthreads();

            // ---- layer 3 partials: thread (g, lane) covers rows [32g, 32g+32) ----
            a0 = 0; a1 = 0;
            const ulonglong2* z2v = (const ulonglong2*)(sz2 + 32*g);  // 8 entries
#pragma unroll
            for (int m = 0; m < 8; m++) {
                ulonglong2 p = z2v[m];
                a0 = ffma2(p.x, w3p[2*m + 0], a0);
                a1 = ffma2(p.y, w3p[2*m + 1], a1);
            }
            f0 = upk2(a0); f1 = upk2(a1);
            sp[j] = (f0.x + f0.y) + (f1.x + f1.y);
            __syncthreads();

            // ---- reduce + RK4 state bookkeeping (warp 0 owns state) ----
            if (j < 32) {
                float xh    = sx[j];  // h passed into this dyn() eval
                float drift = b3k + ((sp[j] + sp[j + 32]) + (sp[j + 64] + sp[j + 96]));
                float dyn   = 0.02f * drift - 0.1f * xh;
                float xn;
                if (s == 0)      { accK  = dyn;         xn = hreg + (0.5f * DTF) * dyn; }
                else if (s == 1) { accK += 2.0f * dyn;  xn = hreg + (0.5f * DTF) * dyn; }
                else if (s == 2) { accK += 2.0f * dyn;  xn = hreg + DTF * dyn; }
                else             { accK += dyn;
                                   xn = tanh_f(hreg + (DTF / 6.0f) * accK);
                                   hreg = xn; }
                sx[j] = xn;
            }
            if (s == 3 && j < 2) {
                ((float4*)(sx + 32))[j] = ubuf;          // u[t+1] into place
                int nt = (t + 2 < TSTEPS) ? (t + 2) : (TSTEPS - 1);
                ubuf = ((const float4*)U)[2*nt + j];     // prefetch u[t+2]
            }
            __syncthreads();
        }
    }

    if (j < 32) out[3 * TSTEPS + j] = hreg;   // h_last
}

// Observer pass: d/t/c = h_t @ W{d,t,c} + b — embarrassingly parallel over t.
__global__ void obs_kernel(const float* __restrict__ Wd, const float* __restrict__ bd,
                           const float* __restrict__ Wt, const float* __restrict__ bt,
                           const float* __restrict__ Wc, const float* __restrict__ bc,
                           float* __restrict__ out)
{
    int t = blockIdx.x * blockDim.x + threadIdx.x;
    if (t >= TSTEPS) return;
    const float4* h4 = (const float4*)(g_hs + (size_t)t * 32);
    float ad = 0.f, at = 0.f, ac = 0.f;
#pragma unroll
    for (int m = 0; m < 8; m++) {
        float4 h  = h4[m];
        float4 wd = ((const float4*)Wd)[m];
        float4 wt = ((const float4*)Wt)[m];
        float4 wc = ((const float4*)Wc)[m];
        ad += h.x*wd.x + h.y*wd.y + h.z*wd.z + h.w*wd.w;
        at += h.x*wt.x + h.y*wt.y + h.z*wt.z + h.w*wt.w;
        ac += h.x*wc.x + h.y*wc.y + h.z*wc.z + h.w*wc.w;
    }
    out[t]              = ad + bd[0];
    out[TSTEPS + t]     = at + bt[0];
    out[2 * TSTEPS + t] = ac + bc[0];
}

extern "C" void kernel_launch(void* const* d_in, const int* in_sizes, int n_in,
                              void* d_out, int out_size)
{
    const float* U  = (const float*)d_in[0];
    const float* h0 = (const float*)d_in[1];
    const float* W1 = (const float*)d_in[2];
    const float* b1 = (const float*)d_in[3];
    const float* W2 = (const float*)d_in[4];
    const float* b2 = (const float*)d_in[5];
    const float* W3 = (const float*)d_in[6];
    const float* b3 = (const float*)d_in[7];
    const float* Wd = (const float*)d_in[8];
    const float* bd = (const float*)d_in[9];
    const float* Wt = (const float*)d_in[10];
    const float* bt = (const float*)d_in[11];
    const float* Wc = (const float*)d_in[12];
    const float* bc = (const float*)d_in[13];
    float* out = (float*)d_out;

    node_scan_kernel<<<1, 128>>>(U, h0, W1, b1, W2, b2, W3, b3, out);
    obs_kernel<<<(TSTEPS + 255) / 256, 256>>>(Wd, bd, Wt, bt, Wc, bc, out);
}

// round 2
// speedup vs baseline: 1.0944x; 1.0944x over previous
#include <cuda_runtime.h>

#define TSTEPS 65536
#define DTF (5.0f/60.0f)

// 8 MB log of h_t (state at the START of step t) for the observer pass.
__device__ float g_hs[(size_t)TSTEPS * 32];

typedef unsigned long long ull;

static __device__ __forceinline__ ull pk2(float lo, float hi) {
    ull r; asm("mov.b64 %0, {%1,%2};" : "=l"(r) : "f"(lo), "f"(hi)); return r;
}
static __device__ __forceinline__ float2 upk2(ull v) {
    float2 r; asm("mov.b64 {%0,%1}, %2;" : "=f"(r.x), "=f"(r.y) : "l"(v)); return r;
}
// Packed fp32x2 FMA / ADD (Blackwell): 2 fp32 ops per instruction.
static __device__ __forceinline__ ull ffma2(ull a, ull b, ull c) {
    ull d; asm("fma.rn.f32x2 %0, %1, %2, %3;" : "=l"(d) : "l"(a), "l"(b), "l"(c)); return d;
}
static __device__ __forceinline__ ull fadd2(ull a, ull b) {
    ull d; asm("add.rn.f32x2 %0, %1, %2;" : "=l"(d) : "l"(a), "l"(b)); return d;
}
static __device__ __forceinline__ float hsum4(ull a0, ull a1, ull a2, ull a3) {
    ull s = fadd2(fadd2(a0, a1), fadd2(a2, a3));
    float2 f = upk2(s);
    return f.x + f.y;
}

static __device__ __forceinline__ float silu_f(float x) {
    float e = __expf(-x);
    return __fdividef(x, 1.0f + e);
}
static __device__ __forceinline__ float tanh_f(float x) {
    float e = __expf(2.0f * x);
    return 1.0f - __fdividef(2.0f, e + 1.0f);
}

__global__ __launch_bounds__(128, 1)
void node_scan_kernel(const float* __restrict__ U, const float* __restrict__ h0,
                      const float* __restrict__ W1, const float* __restrict__ b1,
                      const float* __restrict__ W2, const float* __restrict__ b2,
                      const float* __restrict__ W3, const float* __restrict__ b3,
                      float* __restrict__ out)
{
    __shared__ __align__(16) float sz1[128];
    __shared__ __align__(16) float sz2[128];
    __shared__ __align__(16) float sp[128];     // layer-3 partials (cross-warp)
    __shared__ __align__(16) float sxg[4][32];  // per-warp private h-broadcast
    __shared__ __align__(16) float su[4][8];    // per-warp private u
    __shared__ float sW1u[8 * 128];             // u-rows of W1

    const int j    = threadIdx.x;
    const int lane = j & 31;
    const int g    = j >> 5;

    // ---- register-resident weights (packed fp32 pairs) ----
    ull w1h[16];                                // h-rows of W1, column j
#pragma unroll
    for (int m = 0; m < 16; m++)
        w1h[m] = pk2(W1[(2*m)*128 + j], W1[(2*m+1)*128 + j]);
    const float b1j = b1[j];

    ull w2p[64];
#pragma unroll
    for (int m = 0; m < 64; m++)
        w2p[m] = pk2(W2[(2*m)*128 + j], W2[(2*m+1)*128 + j]);
    const float b2j = b2[j];

    ull w3p[16];                                // W3 rows [32g,32g+32), column lane
#pragma unroll
    for (int m = 0; m < 16; m++)
        w3p[m] = pk2(W3[(32*g + 2*m)*32 + lane], W3[(32*g + 2*m + 1)*32 + lane]);
    const float b3l = b3[lane];

    // u-rows of W1 into shared (used once per step for zu)
#pragma unroll
    for (int m = j; m < 8 * 128; m += 128) sW1u[m] = W1[32*128 + m];

    // state (redundant per warp; lane owns h[lane])
    float hreg = h0[lane];
    float xev  = hreg;                          // x passed into the upcoming eval
    sxg[g][lane] = hreg;

    // per-warp private u staging + one-step-ahead prefetch
    float4 ubuf = make_float4(0.f, 0.f, 0.f, 0.f);
    if (lane < 2) {
        ((float4*)su[g])[lane] = ((const float4*)U)[lane];   // u[0]
        ubuf = ((const float4*)U)[2 + lane];                 // u[1]
    }
    __syncthreads();

    // zu_j = b1[j] + u . W1u[:,j]  (recomputed once per step)
    float zu = b1j;
#pragma unroll
    for (int m = 0; m < 8; m++) zu = fmaf(su[g][m], sW1u[m*128 + j], zu);

    float accK = 0.0f;

#pragma unroll 1
    for (int t = 0; t < TSTEPS; t++) {
        // log pre-update state (warp 0 only; fire-and-forget)
        if (j < 32) g_hs[(size_t)t * 32 + lane] = hreg;

#pragma unroll
        for (int s = 0; s < 4; s++) {
            // ---- layer 1 (h-part): 32 -> 128, + zu, silu ----
            ull a0 = 0, a1 = 0, a2 = 0, a3 = 0;
            const ulonglong2* xv = (const ulonglong2*)sxg[g];   // 8 entries
#pragma unroll
            for (int m = 0; m < 4; m++) {
                ulonglong2 p = xv[2*m];
                ulonglong2 q = xv[2*m + 1];
                a0 = ffma2(p.x, w1h[4*m + 0], a0);
                a1 = ffma2(p.y, w1h[4*m + 1], a1);
                a2 = ffma2(q.x, w1h[4*m + 2], a2);
                a3 = ffma2(q.y, w1h[4*m + 3], a3);
            }
            float z = zu + hsum4(a0, a1, a2, a3);
            sz1[j] = silu_f(z);
            __syncthreads();                                    // BAR_A (all-to-all)

            // ---- layer 2: 128 -> 128, silu ----
            a0 = a1 = a2 = a3 = 0;
            const ulonglong2* zv = (const ulonglong2*)sz1;      // 32 entries
#pragma unroll
            for (int m = 0; m < 16; m++) {
                ulonglong2 p = zv[2*m];
                ulonglong2 q = zv[2*m + 1];
                a0 = ffma2(p.x, w2p[4*m + 0], a0);
                a1 = ffma2(p.y, w2p[4*m + 1], a1);
                a2 = ffma2(q.x, w2p[4*m + 2], a2);
                a3 = ffma2(q.y, w2p[4*m + 3], a3);
            }
            z = b2j + hsum4(a0, a1, a2, a3);
            sz2[j] = silu_f(z);
            __syncwarp();          // layer-3 inputs are own-warp's sz2 chunk only

            // ---- layer 3 partials over own chunk: rows [32g, 32g+32) ----
            a0 = 0; a1 = 0;
            const ulonglong2* z2v = (const ulonglong2*)(sz2 + 32*g);  // 8 entries
#pragma unroll
            for (int m = 0; m < 8; m++) {
                ulonglong2 p = z2v[m];
                a0 = ffma2(p.x, w3p[2*m + 0], a0);
                a1 = ffma2(p.y, w3p[2*m + 1], a1);
            }
            {
                float2 f = upk2(fadd2(a0, a1));
                sp[j] = f.x + f.y;
            }
            __syncthreads();                                    // BAR_B (cross-warp)

            // ---- redundant reduce + RK4 update (every warp, lane owns state) ----
            float drift = b3l + ((sp[lane] + sp[lane + 32]) + (sp[lane + 64] + sp[lane + 96]));
            float dyn   = 0.02f * drift - 0.1f * xev;
            if (s == 0)      { accK  = dyn;        xev = hreg + (0.5f * DTF) * dyn; }
            else if (s == 1) { accK += 2.0f * dyn; xev = hreg + (0.5f * DTF) * dyn; }
            else if (s == 2) { accK += 2.0f * dyn; xev = hreg + DTF * dyn; }
            else {
                accK += dyn;
                hreg = tanh_f(hreg + (DTF / 6.0f) * accK);
                xev  = hreg;
                if (lane < 2) {
                    ((float4*)su[g])[lane] = ubuf;              // u[t+1] in place
                    int nt = (t + 2 < TSTEPS) ? (t + 2) : (TSTEPS - 1);
                    ubuf = ((const float4*)U)[2*nt + lane];     // prefetch u[t+2]
                }
            }
            sxg[g][lane] = xev;
            __syncwarp();

            if (s == 3) {   // refresh zu for the next step (su just updated)
                float zz = b1j;
#pragma unroll
                for (int m = 0; m < 8; m++) zz = fmaf(su[g][m], sW1u[m*128 + j], zz);
                zu = zz;
            }
        }
    }

    if (j < 32) out[3 * TSTEPS + j] = hreg;   // h_last
}

// Observer pass: d/t/c = h_t @ W{d,t,c} + b — embarrassingly parallel over t.
__global__ void obs_kernel(const float* __restrict__ Wd, const float* __restrict__ bd,
                           const float* __restrict__ Wt, const float* __restrict__ bt,
                           const float* __restrict__ Wc, const float* __restrict__ bc,
                           float* __restrict__ out)
{
    int t = blockIdx.x * blockDim.x + threadIdx.x;
    if (t >= TSTEPS) return;
    const float4* h4 = (const float4*)(g_hs + (size_t)t * 32);
    float ad = 0.f, at = 0.f, ac = 0.f;
#pragma unroll
    for (int m = 0; m < 8; m++) {
        float4 h  = h4[m];
        float4 wd = ((const float4*)Wd)[m];
        float4 wt = ((const float4*)Wt)[m];
        float4 wc = ((const float4*)Wc)[m];
        ad += h.x*wd.x + h.y*wd.y + h.z*wd.z + h.w*wd.w;
        at += h.x*wt.x + h.y*wt.y + h.z*wt.z + h.w*wt.w;
        ac += h.x*wc.x + h.y*wc.y + h.z*wc.z + h.w*wc.w;
    }
    out[t]              = ad + bd[0];
    out[TSTEPS + t]     = at + bt[0];
    out[2 * TSTEPS + t] = ac + bc[0];
}

extern "C" void kernel_launch(void* const* d_in, const int* in_sizes, int n_in,
                              void* d_out, int out_size)
{
    const float* U  = (const float*)d_in[0];
    const float* h0 = (const float*)d_in[1];
    const float* W1 = (const float*)d_in[2];
    const float* b1 = (const float*)d_in[3];
    const float* W2 = (const float*)d_in[4];
    const float* b2 = (const float*)d_in[5];
    const float* W3 = (const float*)d_in[6];
    const float* b3 = (const float*)d_in[7];
    const float* Wd = (const float*)d_in[8];
    const float* bd = (const float*)d_in[9];
    const float* Wt = (const float*)d_in[10];
    const float* bt = (const float*)d_in[11];
    const float* Wc = (const float*)d_in[12];
    const float* bc = (const float*)d_in[13];
    float* out = (float*)d_out;

    node_scan_kernel<<<1, 128>>>(U, h0, W1, b1, W2, b2, W3, b3, out);
    obs_kernel<<<(TSTEPS + 255) / 256, 256>>>(Wd, bd, Wt, bt, Wc, bc, out);
}